// round 15
// baseline (speedup 1.0000x reference)
#include <cuda_runtime.h>

#define NN   2048
#define ORD  3
#define PTS  16
#define DIM1 64
#define DIM2 32
#define PL1  32
#define PL2  8
#define LBL  10
#define GRID 760                // 152 SMs x 5 resident blocks
#define NTHR 288                // 8 worker warps + 1 tail warp

// Scratch (zero at module load; self-reset each launch)
__device__ float    g_num[PL2 * DIM2];
__device__ float    g_den[PL2];
__device__ unsigned g_row;      // row steal counter
__device__ unsigned g_done;     // block completion counter

__device__ __forceinline__ float fast_tanh(float x) {
    float r;
    asm("tanh.approx.f32 %0, %1;" : "=f"(r) : "f"(x));
    return r;
}

// cos(2*pi*y): exact reduction + even poly through (2*pi*t)^14, max err ~4e-6
__device__ __forceinline__ float cos2pi(float y) {
    float t = y - rintf(y);
    float u = t * t;
    float p = -1.7143907f;
    p = fmaf(p, u,  7.9035539f);
    p = fmaf(p, u, -26.4257337f);
    p = fmaf(p, u,  60.2446418f);
    p = fmaf(p, u, -85.4567987f);
    p = fmaf(p, u,  64.9393940f);
    p = fmaf(p, u, -19.7392088f);
    p = fmaf(p, u,  1.0f);
    return p;
}

__device__ __forceinline__ int bitrev3(int x) {
    return ((x & 1) << 2) | (x & 2) | ((x & 4) >> 2);
}

__device__ __forceinline__ void bar_sync_n(int id) {
    asm volatile("bar.sync %0, %1;" :: "r"(id), "n"(NTHR) : "memory");
}
__device__ __forceinline__ void bar_arrive_n(int id) {
    asm volatile("bar.arrive %0, %1;" :: "r"(id), "n"(NTHR) : "memory");
}

// ---------------------------------------------------------------------------
// Producer/consumer fused kernel.
//   warps 0-7 (256 thr): pure phase-1 cos pipeline, rows handed to them.
//   warp 8: steals rows, gathers partials, runs MLP+pooling tail, fully
//           overlapped with the workers' next row.
// ---------------------------------------------------------------------------
__global__ __launch_bounds__(NTHR, 5) void k_fused(
    const float* __restrict__ adj, const float* __restrict__ wm,
    const float* __restrict__ w1, const float* __restrict__ b1,
    const float* __restrict__ w2, const float* __restrict__ b2,
    const float* __restrict__ p1, const float* __restrict__ pb1,
    const float* __restrict__ p2, const float* __restrict__ pb2,
    const float* __restrict__ cw, const float* __restrict__ cb,
    float* __restrict__ out) {

    const int tid = threadIdx.x;
    const int warp = tid >> 5, lane = tid & 31;

    __shared__ float s_w [ORD * PTS];
    __shared__ float s_ws[ORD * PTS];
    __shared__ float red[2][ORD][8][PTS];   // double-buffered partials
    __shared__ float s_ms[ORD * PTS];       // tail-warp private
    __shared__ float s_h1[DIM1];
    __shared__ float s_h2[DIM2];
    __shared__ float s_ab[PL1];
    __shared__ volatile int s_r[2];
    __shared__ unsigned s_last;

    if (tid < ORD * PTS) {
        float w = wm[tid];
        s_w[tid]  = w;
        s_ws[tid] = w * 0.15915494309189535f;
    }
    __syncthreads();

    if (warp < 8) {
        // ================= WORKERS: pure MUFU pipeline =================
        int cur = 0;
        for (;;) {
            bar_sync_n(2);                  // s_r[cur] published by tail warp
            const int r = s_r[cur];
            if (r >= NN) break;

            const float* base = adj + (size_t)r * NN;
#pragma unroll
            for (int o = 0; o < ORD; o++) {
                const float4* row = reinterpret_cast<const float4*>(base + (size_t)o * NN * NN);
                const float4 c0 = row[tid];
                const float4 c1 = row[tid + 256];
                const float xs[8] = {c0.x, c0.y, c0.z, c0.w, c1.x, c1.y, c1.z, c1.w};

#pragma unroll
                for (int s = 0; s < 2; s++) {
                    float w[7], acc[8];
#pragma unroll
                    for (int q = 0; q < 7; q++) { w[q] = s_w[o * PTS + s * 8 + q]; acc[q] = 0.f; }
                    const float wsp = s_ws[o * PTS + s * 8 + 7];
                    acc[7] = 0.f;

#pragma unroll
                    for (int e = 0; e < 8; e++) {
                        const float x = xs[e];
#pragma unroll
                        for (int q = 0; q < 7; q++) acc[q] += __cosf(w[q] * x);
                        acc[7] += cos2pi(wsp * x);
                    }

                    // split-butterfly: 8 accs -> 1 per lane (pt = bitrev3(lane&7))
#pragma unroll
                    for (int st = 0; st < 3; st++) {
                        const int bit = 1 << st, half = 8 >> (st + 1);
                        const bool hi = lane & bit;
#pragma unroll
                        for (int q = 0; q < 4; q++) {
                            if (q < half) {
                                float send = hi ? acc[q] : acc[q + half];
                                float recv = __shfl_xor_sync(0xffffffffu, send, bit);
                                acc[q] = (hi ? acc[q + half] : acc[q]) + recv;
                            }
                        }
                    }
                    float v = acc[0];
                    v += __shfl_xor_sync(0xffffffffu, v, 8);
                    v += __shfl_xor_sync(0xffffffffu, v, 16);
                    if (lane < 8) red[cur][o][warp][s * 8 + lane] = v;
                }
            }
            bar_arrive_n(1);                // red[cur] published
            cur ^= 1;
        }
    } else {
        // ================= TAIL WARP: steal / gather / MLP =================
        int r_pend;
        if (lane == 0) s_r[0] = (int)atomicAdd(&g_row, 1u);
        __syncwarp();
        r_pend = s_r[0];
        bar_arrive_n(2);                    // release workers for row 0
        int cur = 0;

        while (r_pend < NN) {
            if (lane == 0) s_r[cur ^ 1] = (int)atomicAdd(&g_row, 1u);  // pre-steal
            __syncwarp();
            const int r_next = s_r[cur ^ 1];
            bar_sync_n(1);                  // red[cur] ready
            bar_arrive_n(2);                // release workers into r_next

            // gather 48 features from red[cur]
            if (lane < 16) {
#pragma unroll
                for (int o = 0; o < ORD; o++) {
                    float s = 0.f;
#pragma unroll
                    for (int wz = 0; wz < 8; wz++) s += red[cur][o][wz][lane];
                    s_ms[o * PTS + (lane & 8) + bitrev3(lane & 7)] = s * (1.0f / NN);
                }
            }
            __syncwarp();

            // ---- warp-private MLP tail (overlaps workers' next row) ----
            {   // h1: 2 outputs per lane
                float a0 = __ldg(b1 + lane), a1 = 0.f, a2 = 0.f, a3 = 0.f;
                float d0 = __ldg(b1 + lane + 32), d1 = 0.f, d2 = 0.f, d3 = 0.f;
#pragma unroll
                for (int k = 0; k < 48; k += 4) {
                    const float m0 = s_ms[k],     m1 = s_ms[k + 1];
                    const float m2 = s_ms[k + 2], m3 = s_ms[k + 3];
                    a0 = fmaf(m0, __ldg(w1 + (k    ) * DIM1 + lane), a0);
                    a1 = fmaf(m1, __ldg(w1 + (k + 1) * DIM1 + lane), a1);
                    a2 = fmaf(m2, __ldg(w1 + (k + 2) * DIM1 + lane), a2);
                    a3 = fmaf(m3, __ldg(w1 + (k + 3) * DIM1 + lane), a3);
                    d0 = fmaf(m0, __ldg(w1 + (k    ) * DIM1 + lane + 32), d0);
                    d1 = fmaf(m1, __ldg(w1 + (k + 1) * DIM1 + lane + 32), d1);
                    d2 = fmaf(m2, __ldg(w1 + (k + 2) * DIM1 + lane + 32), d2);
                    d3 = fmaf(m3, __ldg(w1 + (k + 3) * DIM1 + lane + 32), d3);
                }
                s_h1[lane]      = fmaxf((a0 + a1) + (a2 + a3), 0.f);
                s_h1[lane + 32] = fmaxf((d0 + d1) + (d2 + d3), 0.f);
            }
            __syncwarp();

            float h2v;
            {   // h2
                float a0 = __ldg(b2 + lane), a1 = 0.f, a2 = 0.f, a3 = 0.f;
#pragma unroll
                for (int k = 0; k < DIM1; k += 4) {
                    a0 = fmaf(s_h1[k],     __ldg(w2 + (k    ) * DIM2 + lane), a0);
                    a1 = fmaf(s_h1[k + 1], __ldg(w2 + (k + 1) * DIM2 + lane), a1);
                    a2 = fmaf(s_h1[k + 2], __ldg(w2 + (k + 2) * DIM2 + lane), a2);
                    a3 = fmaf(s_h1[k + 3], __ldg(w2 + (k + 3) * DIM2 + lane), a3);
                }
                h2v = fmaxf((a0 + a1) + (a2 + a3), 0.f);
                s_h2[lane] = h2v;
            }
            __syncwarp();

            {   // abstract
                float a0 = __ldg(pb1 + lane), a1 = 0.f, a2 = 0.f, a3 = 0.f;
#pragma unroll
                for (int k = 0; k < DIM2; k += 4) {
                    a0 = fmaf(s_h2[k],     __ldg(p1 + (k    ) * PL1 + lane), a0);
                    a1 = fmaf(s_h2[k + 1], __ldg(p1 + (k + 1) * PL1 + lane), a1);
                    a2 = fmaf(s_h2[k + 2], __ldg(p1 + (k + 2) * PL1 + lane), a2);
                    a3 = fmaf(s_h2[k + 3], __ldg(p1 + (k + 3) * PL1 + lane), a3);
                }
                s_ab[lane] = fast_tanh((a0 + a1) + (a2 + a3));
            }
            __syncwarp();

            float e = 0.f;
            if (lane < PL2) {               // attention logits -> exp
                float a0 = __ldg(pb2 + lane), a1 = 0.f, a2 = 0.f, a3 = 0.f;
#pragma unroll
                for (int k = 0; k < PL1; k += 4) {
                    a0 = fmaf(s_ab[k],     __ldg(p2 + (k    ) * PL2 + lane), a0);
                    a1 = fmaf(s_ab[k + 1], __ldg(p2 + (k + 1) * PL2 + lane), a1);
                    a2 = fmaf(s_ab[k + 2], __ldg(p2 + (k + 2) * PL2 + lane), a2);
                    a3 = fmaf(s_ab[k + 3], __ldg(p2 + (k + 3) * PL2 + lane), a3);
                }
                e = __expf((a0 + a1) + (a2 + a3));  // |s| small: safe unshifted
            }
            __syncwarp();

            // pooling: broadcast e[c], each lane adds its d-column
#pragma unroll
            for (int c = 0; c < PL2; c++) {
                const float ec = __shfl_sync(0xffffffffu, e, c);
                atomicAdd(&g_num[c * DIM2 + lane], ec * h2v);
            }
            if (lane < PL2) atomicAdd(&g_den[lane], e);

            r_pend = r_next;
            cur ^= 1;
        }
    }

    // ---- block done; last block computes the head ----
    __threadfence();
    __syncthreads();
    if (tid == 0) s_last = (atomicAdd(&g_done, 1u) == GRID - 1u) ? 1u : 0u;
    __syncthreads();
    if (!s_last) return;

    __shared__ float part[8][LBL];
    if (tid < PL2 * DIM2) {
        float v = __ldcg(&g_num[tid]) / __ldcg(&g_den[tid >> 5]);
        float p[LBL];
#pragma unroll
        for (int l = 0; l < LBL; l++) p[l] = v * __ldg(cw + tid * LBL + l);
#pragma unroll
        for (int ofs = 16; ofs; ofs >>= 1)
#pragma unroll
            for (int l = 0; l < LBL; l++)
                p[l] += __shfl_xor_sync(0xffffffffu, p[l], ofs);
        if (lane == 0) {
#pragma unroll
            for (int l = 0; l < LBL; l++) part[warp][l] = p[l];
        }
    }
    __syncthreads();

    if (tid < 32) {
        float logit = -1e30f;
        if (tid < LBL) {
            float a = __ldg(cb + tid);
#pragma unroll
            for (int wz = 0; wz < 8; wz++) a += part[wz][tid];
            logit = a;
        }
        float m2 = logit;
#pragma unroll
        for (int ofs = 16; ofs; ofs >>= 1)
            m2 = fmaxf(m2, __shfl_xor_sync(0xffffffffu, m2, ofs));
        float ex = (tid < LBL) ? expf(logit - m2) : 0.f;
        float s2 = ex;
#pragma unroll
        for (int ofs = 16; ofs; ofs >>= 1)
            s2 += __shfl_xor_sync(0xffffffffu, s2, ofs);
        if (tid < LBL) out[tid] = logit - m2 - logf(s2);
    }
    __syncthreads();

    // reset for next graph replay (all reads above complete)
    if (tid < PL2 * DIM2) __stcg(&g_num[tid], 0.f);
    if (tid < PL2) __stcg(&g_den[tid], 0.f);
    if (tid == 0) {
        __threadfence();
        atomicExch(&g_row, 0u);
        atomicExch(&g_done, 0u);
    }
}

// ---------------------------------------------------------------------------
extern "C" void kernel_launch(void* const* d_in, const int* in_sizes, int n_in,
                              void* d_out, int out_size) {
    const float* adj = (const float*)d_in[0];
    const float* wm  = (const float*)d_in[1];
    const float* w1  = (const float*)d_in[2];
    const float* b1  = (const float*)d_in[3];
    const float* w2  = (const float*)d_in[4];
    const float* b2  = (const float*)d_in[5];
    const float* p1  = (const float*)d_in[6];
    const float* pb1 = (const float*)d_in[7];
    const float* p2  = (const float*)d_in[8];
    const float* pb2 = (const float*)d_in[9];
    const float* cw  = (const float*)d_in[10];
    const float* cb  = (const float*)d_in[11];
    float* out = (float*)d_out;

    k_fused<<<GRID, NTHR>>>(adj, wm, w1, b1, w2, b2, p1, pb1, p2, pb2, cw, cb, out);
}

// round 17
// speedup vs baseline: 1.1366x; 1.1366x over previous
#include <cuda_runtime.h>
#include <cstdint>

#define NN   2048
#define ORD  3
#define PTS  16
#define DIM1 64
#define DIM2 32
#define PL1  32
#define PL2  8
#define LBL  10

// Scratch accumulators (zero at module load; self-reset each launch)
__device__ float    g_num[PL2 * DIM2];
__device__ float    g_den[PL2];
__device__ unsigned g_cnt;

__device__ __forceinline__ float fast_tanh(float x) {
    float r;
    asm("tanh.approx.f32 %0, %1;" : "=f"(r) : "f"(x));
    return r;
}

// cos(2*pi*y): exact reduction + even poly through (2*pi*t)^14, max err ~4e-6
__device__ __forceinline__ float cos2pi(float y) {
    float t = y - rintf(y);
    float u = t * t;
    float p = -1.7143907f;
    p = fmaf(p, u,  7.9035539f);
    p = fmaf(p, u, -26.4257337f);
    p = fmaf(p, u,  60.2446418f);
    p = fmaf(p, u, -85.4567987f);
    p = fmaf(p, u,  64.9393940f);
    p = fmaf(p, u, -19.7392088f);
    p = fmaf(p, u,  1.0f);
    return p;
}

__device__ __forceinline__ int bitrev3(int x) {
    return ((x & 1) << 2) | (x & 2) | ((x & 4) >> 2);
}

__device__ __forceinline__ void cp_async16(void* smem_dst, const void* gmem_src) {
    unsigned int s = (unsigned int)__cvta_generic_to_shared(smem_dst);
    asm volatile("cp.async.ca.shared.global [%0], [%1], 16;"
                 :: "r"(s), "l"(gmem_src) : "memory");
}
__device__ __forceinline__ void cp_commit() {
    asm volatile("cp.async.commit_group;" ::: "memory");
}
template <int N>
__device__ __forceinline__ void cp_wait() {
    asm volatile("cp.async.wait_group %0;" :: "n"(N) : "memory");
}

// ---------------------------------------------------------------------------
// Fused kernel (R5 body + cp.async order-pipelined staging).
// One block (256 thr, 6/SM) per node row. Order o+1's data streams into smem
// while order o computes; per-thread self-staging -> no barrier in the stream.
// ---------------------------------------------------------------------------
__global__ __launch_bounds__(256, 6) void k_fused(
    const float* __restrict__ adj, const float* __restrict__ wm,
    const float* __restrict__ w1, const float* __restrict__ b1,
    const float* __restrict__ w2, const float* __restrict__ b2,
    const float* __restrict__ p1, const float* __restrict__ pb1,
    const float* __restrict__ p2, const float* __restrict__ pb2,
    const float* __restrict__ cw, const float* __restrict__ cb,
    float* __restrict__ out) {

    const int i = blockIdx.x, tid = threadIdx.x;
    const int warp = tid >> 5, lane = tid & 31;

    __shared__ float4 stage[2][2][256];   // [buf][half][tid] : 16 KB
    __shared__ float s_w [ORD * PTS];
    __shared__ float s_ws[ORD * PTS];
    __shared__ float red[ORD][8][PTS];
    __shared__ float s_ms[ORD * PTS];
    __shared__ float s_h1[DIM1];
    __shared__ float s_h2[DIM2];
    __shared__ float s_ab[PL1];
    __shared__ float s_s[PL2];

    if (tid < ORD * PTS) {
        float w = wm[tid];
        s_w[tid]  = w;
        s_ws[tid] = w * 0.15915494309189535f;
    }

    const float* base = adj + (size_t)i * NN;

    // stage order 0
    {
        const float4* row = reinterpret_cast<const float4*>(base);
        cp_async16(&stage[0][0][tid], row + tid);
        cp_async16(&stage[0][1][tid], row + tid + 256);
        cp_commit();
    }
    __syncthreads();   // covers s_w/s_ws publication (overlaps the stage-0 fill)

    // ---- phase 1: characteristic features, order-pipelined ----
#pragma unroll
    for (int o = 0; o < ORD; o++) {
        if (o < ORD - 1) {
            const float4* nrow = reinterpret_cast<const float4*>(
                base + (size_t)(o + 1) * NN * NN);
            cp_async16(&stage[(o + 1) & 1][0][tid], nrow + tid);
            cp_async16(&stage[(o + 1) & 1][1][tid], nrow + tid + 256);
            cp_commit();
            cp_wait<1>();   // buf[o&1] (previous group) complete
        } else {
            cp_wait<0>();
        }

        const float4 c0 = stage[o & 1][0][tid];
        const float4 c1 = stage[o & 1][1][tid];
        const float xs[8] = {c0.x, c0.y, c0.z, c0.w, c1.x, c1.y, c1.z, c1.w};

#pragma unroll
        for (int s = 0; s < 2; s++) {
            float w[7], acc[8];
#pragma unroll
            for (int q = 0; q < 7; q++) { w[q] = s_w[o * PTS + s * 8 + q]; acc[q] = 0.f; }
            const float wsp = s_ws[o * PTS + s * 8 + 7];
            acc[7] = 0.f;

#pragma unroll
            for (int e = 0; e < 8; e++) {
                const float x = xs[e];
#pragma unroll
                for (int q = 0; q < 7; q++) acc[q] += __cosf(w[q] * x);
                acc[7] += cos2pi(wsp * x);
            }

            // split-butterfly: 8 accs -> 1 per lane (point = bitrev3(lane&7))
#pragma unroll
            for (int st = 0; st < 3; st++) {
                const int bit = 1 << st, half = 8 >> (st + 1);
                const bool hi = lane & bit;
#pragma unroll
                for (int q = 0; q < 4; q++) {
                    if (q < half) {
                        float send = hi ? acc[q] : acc[q + half];
                        float recv = __shfl_xor_sync(0xffffffffu, send, bit);
                        acc[q] = (hi ? acc[q + half] : acc[q]) + recv;
                    }
                }
            }
            float v = acc[0];
            v += __shfl_xor_sync(0xffffffffu, v, 8);
            v += __shfl_xor_sync(0xffffffffu, v, 16);
            if (lane < 8) red[o][warp][s * 8 + lane] = v;
        }
    }
    __syncthreads();

    if (tid < ORD * PTS) {
        const int o = tid >> 4, l = tid & 15;
        float s = 0.f;
#pragma unroll
        for (int wz = 0; wz < 8; wz++) s += red[o][wz][l];
        s_ms[o * PTS + (l & 8) + bitrev3(l & 7)] = s * (1.0f / NN);
    }
    __syncthreads();

    // ---- phase 2: per-row MLP chain (weights L1/L2-resident) ----
    if (tid < DIM1) {
        float a = __ldg(b1 + tid);
#pragma unroll
        for (int k = 0; k < ORD * PTS; k++) a = fmaf(s_ms[k], __ldg(w1 + k * DIM1 + tid), a);
        s_h1[tid] = fmaxf(a, 0.f);
    }
    __syncthreads();

    if (tid < DIM2) {
        float a = __ldg(b2 + tid);
#pragma unroll
        for (int k = 0; k < DIM1; k++) a = fmaf(s_h1[k], __ldg(w2 + k * DIM2 + tid), a);
        s_h2[tid] = fmaxf(a, 0.f);
    }
    __syncthreads();

    if (tid < PL1) {
        float a = __ldg(pb1 + tid);
#pragma unroll
        for (int k = 0; k < DIM2; k++) a = fmaf(s_h2[k], __ldg(p1 + k * PL1 + tid), a);
        s_ab[tid] = fast_tanh(a);
    }
    __syncthreads();

    if (tid < PL2) {
        float a = __ldg(pb2 + tid);
#pragma unroll
        for (int k = 0; k < PL1; k++) a = fmaf(s_ab[k], __ldg(p2 + k * PL2 + tid), a);
        s_s[tid] = a;
    }
    __syncthreads();

    // ---- phase 3: unnormalized softmax pooling via atomics ----
    {
        const int c = tid >> 5, d = tid & 31;
        float e = __expf(s_s[c]);               // |s| small: safe unshifted
        atomicAdd(&g_num[tid], e * s_h2[d]);
        if (d == 0) atomicAdd(&g_den[c], e);
    }

    // ---- phase 4: last block computes the head ----
    __shared__ unsigned s_last;
    __threadfence();
    __syncthreads();
    if (tid == 0) s_last = (atomicAdd(&g_cnt, 1u) == NN - 1u) ? 1u : 0u;
    __syncthreads();
    if (!s_last) return;

    __shared__ float part[8][LBL];
    float v = __ldcg(&g_num[tid]) / __ldcg(&g_den[tid >> 5]);
    {
        float p[LBL];
#pragma unroll
        for (int l = 0; l < LBL; l++) p[l] = v * __ldg(cw + tid * LBL + l);
#pragma unroll
        for (int ofs = 16; ofs; ofs >>= 1)
#pragma unroll
            for (int l = 0; l < LBL; l++)
                p[l] += __shfl_xor_sync(0xffffffffu, p[l], ofs);
        if (lane == 0) {
#pragma unroll
            for (int l = 0; l < LBL; l++) part[warp][l] = p[l];
        }
    }
    __syncthreads();

    if (tid < 32) {
        float logit = -1e30f;
        if (tid < LBL) {
            float a = __ldg(cb + tid);
#pragma unroll
            for (int wz = 0; wz < 8; wz++) a += part[wz][tid];
            logit = a;
        }
        float m2 = logit;
#pragma unroll
        for (int ofs = 16; ofs; ofs >>= 1)
            m2 = fmaxf(m2, __shfl_xor_sync(0xffffffffu, m2, ofs));
        float ex = (tid < LBL) ? expf(logit - m2) : 0.f;
        float s2 = ex;
#pragma unroll
        for (int ofs = 16; ofs; ofs >>= 1)
            s2 += __shfl_xor_sync(0xffffffffu, s2, ofs);
        if (tid < LBL) out[tid] = logit - m2 - logf(s2);
    }
    __syncthreads();

    // reset accumulators for next graph replay
    __stcg(&g_num[tid], 0.f);
    if (tid < PL2) __stcg(&g_den[tid], 0.f);
    if (tid == 0) { __threadfence(); atomicExch(&g_cnt, 0u); }
}

// ---------------------------------------------------------------------------
extern "C" void kernel_launch(void* const* d_in, const int* in_sizes, int n_in,
                              void* d_out, int out_size) {
    const float* adj = (const float*)d_in[0];
    const float* wm  = (const float*)d_in[1];
    const float* w1  = (const float*)d_in[2];
    const float* b1  = (const float*)d_in[3];
    const float* w2  = (const float*)d_in[4];
    const float* b2  = (const float*)d_in[5];
    const float* p1  = (const float*)d_in[6];
    const float* pb1 = (const float*)d_in[7];
    const float* p2  = (const float*)d_in[8];
    const float* pb2 = (const float*)d_in[9];
    const float* cw  = (const float*)d_in[10];
    const float* cb  = (const float*)d_in[11];
    float* out = (float*)d_out;

    k_fused<<<NN, 256>>>(adj, wm, w1, b1, w2, b2, p1, pb1, p2, pb2, cw, cb, out);
}